// round 13
// baseline (speedup 1.0000x reference)
#include <cuda_runtime.h>
#include <math.h>

// Problem constants (fixed by the reference)
#define NROWS 25088     // B*H*W
#define DIM   64
#define KNEG  100
#define HW    3136      // H*W
#define DHW   200704    // D*H*W

// Scratch (no cudaMalloc allowed)
__device__ signed char g_x1q[NROWS * DIM];   // normalized x1, int8 (x*127), 1.6MB
__device__ float       g_pos[NROWS];
__device__ float       g_loss[NROWS];

// ---------------------------------------------------------------------------
// Kernel A (round-4 proven layout, int8 output): Block = 256 threads = 8
// warps handles 32 rows. Warp w owns dims [8w, 8w+8) for all 32 rows; lane =
// row-within-block. Every global load is one 128B warp transaction.
// ---------------------------------------------------------------------------
__global__ void normalize_kernel(const float* __restrict__ x1,
                                 const float* __restrict__ x2) {
    __shared__ float s1s[8][32];
    __shared__ float s2s[8][32];
    __shared__ float pss[8][32];

    int lane = threadIdx.x & 31;   // row within block
    int part = threadIdx.x >> 5;   // dim chunk (warp id)
    int n = blockIdx.x * 32 + lane;
    int b  = n / HW;
    int hw = n - b * HW;
    const float* p1 = x1 + (size_t)b * DHW + (size_t)(part * 8) * HW + hw;
    const float* p2 = x2 + (size_t)b * DHW + (size_t)(part * 8) * HW + hw;

    float v1[8], v2[8];
    #pragma unroll
    for (int i = 0; i < 8; i++) v1[i] = p1[i * HW];
    #pragma unroll
    for (int i = 0; i < 8; i++) v2[i] = p2[i * HW];

    float s1 = 0.f, s2 = 0.f;
    #pragma unroll
    for (int i = 0; i < 8; i++) {
        s1 = fmaf(v1[i], v1[i], s1);
        s2 = fmaf(v2[i], v2[i], s2);
    }
    s1s[part][lane] = s1;
    s2s[part][lane] = s2;
    __syncthreads();

    float t1 = 0.f, t2 = 0.f;
    #pragma unroll
    for (int p = 0; p < 8; p++) { t1 += s1s[p][lane]; t2 += s2s[p][lane]; }
    float sc1 = 1.0f / fmaxf(sqrtf(t1), 1e-12f);
    float sc2 = 1.0f / fmaxf(sqrtf(t2), 1e-12f);

    float pos = 0.f;
    unsigned int w0 = 0, w1 = 0;
    #pragma unroll
    for (int i = 0; i < 8; i++) {
        float a = v1[i] * sc1;
        float c = v2[i] * sc2;
        pos += __expf(a * c);
        unsigned int q = (unsigned int)(__float2int_rn(a * 127.0f)) & 0xffu;
        if (i < 4) w0 |= q << (8 * i);
        else       w1 |= q << (8 * (i - 4));
    }
    *(uint2*)(g_x1q + (size_t)n * DIM + part * 8) = make_uint2(w0, w1);

    pss[part][lane] = pos;
    __syncthreads();
    if (part == 0) {
        float pt = 0.f;
        #pragma unroll
        for (int p = 0; p < 8; p++) pt += pss[p][lane];
        g_pos[n] = pt;
    }
}

// ---------------------------------------------------------------------------
// Kernel B: negatives via IMMA. One warp per row. 7 tiles x 16 negatives:
// gather 16 rows (64B each) into smem (80B stride -> conflict-free LDS),
// 2-stage cp.async per-warp pipeline, then 2x mma.m16n8k32.s8 per tile with
// the query replicated across all 8 B columns. Lane g (=lane>>2) reads dots
// for tile-negatives g and g+8 from d0/d2; all 4 t-duplicates accumulate and
// the final sum is divided by 4.
// ---------------------------------------------------------------------------
__global__ void __launch_bounds__(256) neg_kernel(const int* __restrict__ neg_idx) {
    __shared__ int sidx[8][112];
    __shared__ __align__(16) unsigned char stage[8][2][1280];  // 16 rows * 80B * 2 bufs

    int warp = threadIdx.x >> 5;
    int lane = threadIdx.x & 31;
    int n = blockIdx.x * 8 + warp;
    int g = lane >> 2;   // fragment group (row pair g, g+8)
    int t = lane & 3;    // thread-in-group (16B chunk / k-slice)

    #pragma unroll
    for (int k = lane; k < 112; k += 32)
        sidx[warp][k] = neg_idx[(size_t)n * KNEG + (k < KNEG ? k : KNEG - 1)];
    __syncwarp();

    // Query B-fragments (all 8 columns identical): words t, 4+t (k 0..31)
    // and 8+t, 12+t (k 32..63) of the 64B query row.
    const unsigned int* qw = (const unsigned int*)(g_x1q + (size_t)n * DIM);
    unsigned int b00 = qw[t],     b01 = qw[4 + t];
    unsigned int b10 = qw[8 + t], b11 = qw[12 + t];

    unsigned int sbase = (unsigned int)__cvta_generic_to_shared(&stage[warp][0][0]);

    // Gather one tile: lane loads chunk t (16B) of rows g and g+8.
    #define ISSUE_TILE(tile, buf)                                              \
    do {                                                                       \
        int j0 = sidx[warp][(tile) * 16 + g];                                  \
        int j1 = sidx[warp][(tile) * 16 + 8 + g];                              \
        unsigned int d0 = sbase + (buf) * 1280u + g * 80u + t * 16u;           \
        unsigned int d1 = sbase + (buf) * 1280u + (g + 8) * 80u + t * 16u;     \
        const void* s0 = (const void*)(g_x1q + (size_t)j0 * DIM + t * 16);     \
        const void* s1 = (const void*)(g_x1q + (size_t)j1 * DIM + t * 16);     \
        asm volatile("cp.async.cg.shared.global [%0], [%1], 16;\n"             \
                     :: "r"(d0), "l"(s0) : "memory");                          \
        asm volatile("cp.async.cg.shared.global [%0], [%1], 16;\n"             \
                     :: "r"(d1), "l"(s1) : "memory");                          \
    } while (0)

    ISSUE_TILE(0, 0);
    asm volatile("cp.async.commit_group;\n" ::: "memory");

    float negacc = 0.f;
    const float scale = 1.0f / 16129.0f;   // 1/127^2

    #pragma unroll
    for (int tile = 0; tile < 7; tile++) {
        if (tile < 6) ISSUE_TILE(tile + 1, (tile + 1) & 1);
        asm volatile("cp.async.commit_group;\n" ::: "memory");
        asm volatile("cp.async.wait_group 1;\n" ::: "memory");
        __syncwarp();

        const unsigned int* buf = (const unsigned int*)&stage[warp][tile & 1][0];
        // A fragments (80B row stride = 20 words): rows g, g+8.
        unsigned int a0 = buf[20 * g + t];
        unsigned int a1 = buf[20 * (g + 8) + t];
        unsigned int a2 = buf[20 * g + 4 + t];
        unsigned int a3 = buf[20 * (g + 8) + 4 + t];
        unsigned int a4 = buf[20 * g + 8 + t];
        unsigned int a5 = buf[20 * (g + 8) + 8 + t];
        unsigned int a6 = buf[20 * g + 12 + t];
        unsigned int a7 = buf[20 * (g + 8) + 12 + t];

        int d0 = 0, d1 = 0, d2 = 0, d3 = 0;
        asm volatile(
            "mma.sync.aligned.m16n8k32.row.col.s32.s8.s8.s32 "
            "{%0,%1,%2,%3}, {%4,%5,%6,%7}, {%8,%9}, {%0,%1,%2,%3};\n"
            : "+r"(d0), "+r"(d1), "+r"(d2), "+r"(d3)
            : "r"(a0), "r"(a1), "r"(a2), "r"(a3), "r"(b00), "r"(b01));
        asm volatile(
            "mma.sync.aligned.m16n8k32.row.col.s32.s8.s8.s32 "
            "{%0,%1,%2,%3}, {%4,%5,%6,%7}, {%8,%9}, {%0,%1,%2,%3};\n"
            : "+r"(d0), "+r"(d1), "+r"(d2), "+r"(d3)
            : "r"(a4), "r"(a5), "r"(a6), "r"(a7), "r"(b10), "r"(b11));

        // d0 = dot(neg tile*16+g), d2 = dot(neg tile*16+8+g); cols duplicated.
        float p0 = (float)d0 * scale;
        float p1 = (float)d2 * scale;
        float e0 = __expf(p0);
        float e1 = __expf(p1);
        int k0 = tile * 16 + g;
        negacc += (k0     < KNEG ? e0 : 0.f);
        negacc += (k0 + 8 < KNEG ? e1 : 0.f);
    }
    #undef ISSUE_TILE

    // Each negative counted by 4 t-duplicate lanes -> full butterfly, /4.
    #pragma unroll
    for (int m = 1; m <= 16; m <<= 1)
        negacc += __shfl_xor_sync(0xffffffffu, negacc, m);
    negacc *= 0.25f;

    if (lane == 0) {
        float pos = g_pos[n];
        g_loss[n] = logf(pos + negacc) - logf(pos);
    }
}

// ---------------------------------------------------------------------------
// Kernel C: deterministic mean reduction, single block, float4 loads.
// ---------------------------------------------------------------------------
__global__ void reduce_kernel(float* __restrict__ out) {
    __shared__ float sb[1024];
    const float4* lv = (const float4*)g_loss;   // 25088 = 6272 * 4
    float s = 0.f;
    for (int i = threadIdx.x; i < NROWS / 4; i += 1024) {
        float4 v = lv[i];
        s += (v.x + v.y) + (v.z + v.w);
    }
    sb[threadIdx.x] = s;
    __syncthreads();
    #pragma unroll
    for (int stride = 512; stride > 0; stride >>= 1) {
        if (threadIdx.x < stride) sb[threadIdx.x] += sb[threadIdx.x + stride];
        __syncthreads();
    }
    if (threadIdx.x == 0) out[0] = sb[0] / (float)NROWS;
}

extern "C" void kernel_launch(void* const* d_in, const int* in_sizes, int n_in,
                              void* d_out, int out_size) {
    const float* x1      = (const float*)d_in[0];
    const float* x2      = (const float*)d_in[1];
    const int*   neg_idx = (const int*)  d_in[2];
    float*       out     = (float*)d_out;

    normalize_kernel<<<NROWS / 32, 256>>>(x1, x2);
    neg_kernel<<<NROWS / 8, 256>>>(neg_idx);
    reduce_kernel<<<1, 1024>>>(out);
}

// round 14
// speedup vs baseline: 1.2220x; 1.2220x over previous
#include <cuda_runtime.h>
#include <math.h>

// Problem constants (fixed by the reference)
#define NROWS 25088     // B*H*W
#define DIM   64
#define KNEG  100
#define HW    3136      // H*W
#define DHW   200704    // D*H*W

// Scratch (no cudaMalloc allowed)
__device__ signed char g_x1q[NROWS * DIM];   // normalized x1, int8 (x*127), 1.6MB
__device__ float       g_pos[NROWS];
__device__ float       g_loss[NROWS];

// ---------------------------------------------------------------------------
// Kernel A (round-4 proven layout, int8 output — validated r13): Block = 256
// threads = 8 warps handles 32 rows. Warp w owns dims [8w, 8w+8) for all 32
// rows; lane = row-within-block. Every global load is one 128B transaction.
// ---------------------------------------------------------------------------
__global__ void normalize_kernel(const float* __restrict__ x1,
                                 const float* __restrict__ x2) {
    __shared__ float s1s[8][32];
    __shared__ float s2s[8][32];
    __shared__ float pss[8][32];

    int lane = threadIdx.x & 31;   // row within block
    int part = threadIdx.x >> 5;   // dim chunk (warp id)
    int n = blockIdx.x * 32 + lane;
    int b  = n / HW;
    int hw = n - b * HW;
    const float* p1 = x1 + (size_t)b * DHW + (size_t)(part * 8) * HW + hw;
    const float* p2 = x2 + (size_t)b * DHW + (size_t)(part * 8) * HW + hw;

    float v1[8], v2[8];
    #pragma unroll
    for (int i = 0; i < 8; i++) v1[i] = p1[i * HW];
    #pragma unroll
    for (int i = 0; i < 8; i++) v2[i] = p2[i * HW];

    float s1 = 0.f, s2 = 0.f;
    #pragma unroll
    for (int i = 0; i < 8; i++) {
        s1 = fmaf(v1[i], v1[i], s1);
        s2 = fmaf(v2[i], v2[i], s2);
    }
    s1s[part][lane] = s1;
    s2s[part][lane] = s2;
    __syncthreads();

    float t1 = 0.f, t2 = 0.f;
    #pragma unroll
    for (int p = 0; p < 8; p++) { t1 += s1s[p][lane]; t2 += s2s[p][lane]; }
    float sc1 = 1.0f / fmaxf(sqrtf(t1), 1e-12f);
    float sc2 = 1.0f / fmaxf(sqrtf(t2), 1e-12f);

    float pos = 0.f;
    unsigned int w0 = 0, w1 = 0;
    #pragma unroll
    for (int i = 0; i < 8; i++) {
        float a = v1[i] * sc1;
        float c = v2[i] * sc2;
        pos += __expf(a * c);
        unsigned int q = (unsigned int)(__float2int_rn(a * 127.0f)) & 0xffu;
        if (i < 4) w0 |= q << (8 * i);
        else       w1 |= q << (8 * (i - 4));
    }
    *(uint2*)(g_x1q + (size_t)n * DIM + part * 8) = make_uint2(w0, w1);

    pss[part][lane] = pos;
    __syncthreads();
    if (part == 0) {
        float pt = 0.f;
        #pragma unroll
        for (int p = 0; p < 8; p++) pt += pss[p][lane];
        g_pos[n] = pt;
    }
}

// ---------------------------------------------------------------------------
// Kernel B (round-4 proven structure, DP4A math): negatives over the int8
// table. One warp per row; 8 groups of 4 lanes each handle one k
// concurrently. Lane loads uint4 (16 int8 = 16B) via LDG.128 (proven cheap);
// dot = 4 DP4A (was 8 cvt + 8 HFMA2); 2-shuffle butterfly in the 4-lane
// group; exp uniform; per-row loss to g_loss.
// ---------------------------------------------------------------------------
__global__ void neg_kernel(const int* __restrict__ neg_idx) {
    __shared__ int sidx[8][KNEG];
    int warp = threadIdx.x >> 5;
    int lane = threadIdx.x & 31;
    int n = blockIdx.x * 8 + warp;

    for (int k = lane; k < KNEG; k += 32)
        sidx[warp][k] = neg_idx[(size_t)n * KNEG + k];
    __syncwarp();

    int grp = lane >> 2;  // which of 8 concurrent k's
    int sub = lane & 3;   // 16-dim chunk

    // query chunk: 16 int8 = 4 packed words
    int4 qv = ((const int4*)(g_x1q + (size_t)n * DIM))[sub];

    const float scale = 1.0f / 16129.0f;   // 1/127^2
    float negacc = 0.f;
    #pragma unroll
    for (int it = 0; it < 13; it++) {
        int k = it * 8 + grp;
        bool valid = (k < KNEG);
        int j = sidx[warp][valid ? k : (KNEG - 1)];
        int4 bv = ((const int4*)(g_x1q + (size_t)j * DIM))[sub];
        int acc = 0;
        acc = __dp4a(qv.x, bv.x, acc);
        acc = __dp4a(qv.y, bv.y, acc);
        acc = __dp4a(qv.z, bv.z, acc);
        acc = __dp4a(qv.w, bv.w, acc);
        float p = (float)acc;
        p += __shfl_xor_sync(0xffffffffu, p, 2);
        p += __shfl_xor_sync(0xffffffffu, p, 1);
        float e = __expf(p * scale);
        negacc += valid ? e : 0.f;
    }
    negacc += __shfl_xor_sync(0xffffffffu, negacc, 4);
    negacc += __shfl_xor_sync(0xffffffffu, negacc, 8);
    negacc += __shfl_xor_sync(0xffffffffu, negacc, 16);

    if (lane == 0) {
        float pos = g_pos[n];
        g_loss[n] = logf(pos + negacc) - logf(pos);
    }
}

// ---------------------------------------------------------------------------
// Kernel C: deterministic mean reduction, single block, float4 loads.
// ---------------------------------------------------------------------------
__global__ void reduce_kernel(float* __restrict__ out) {
    __shared__ float sb[1024];
    const float4* lv = (const float4*)g_loss;   // 25088 = 6272 * 4
    float s = 0.f;
    for (int i = threadIdx.x; i < NROWS / 4; i += 1024) {
        float4 v = lv[i];
        s += (v.x + v.y) + (v.z + v.w);
    }
    sb[threadIdx.x] = s;
    __syncthreads();
    #pragma unroll
    for (int stride = 512; stride > 0; stride >>= 1) {
        if (threadIdx.x < stride) sb[threadIdx.x] += sb[threadIdx.x + stride];
        __syncthreads();
    }
    if (threadIdx.x == 0) out[0] = sb[0] / (float)NROWS;
}

extern "C" void kernel_launch(void* const* d_in, const int* in_sizes, int n_in,
                              void* d_out, int out_size) {
    const float* x1      = (const float*)d_in[0];
    const float* x2      = (const float*)d_in[1];
    const int*   neg_idx = (const int*)  d_in[2];
    float*       out     = (float*)d_out;

    normalize_kernel<<<NROWS / 32, 256>>>(x1, x2);
    neg_kernel<<<NROWS / 8, 256>>>(neg_idx);
    reduce_kernel<<<1, 1024>>>(out);
}

// round 15
// speedup vs baseline: 1.3113x; 1.0731x over previous
#include <cuda_runtime.h>
#include <math.h>

// Problem constants (fixed by the reference)
#define NROWS 25088     // B*H*W
#define DIM   64
#define KNEG  100
#define HW    3136      // H*W
#define DHW   200704    // D*H*W
#define NCHUNK_A (NROWS / 32)   // 784  normalize chunks (32 rows each)
#define NCHUNK_B (NROWS / 8)    // 3136 negative chunks (8 rows each)
#define FXSCALE  274877906944.0f // 2^38 fixed-point scale

// Scratch (no cudaMalloc allowed)
__device__ signed char        g_x1q[NROWS * DIM];  // normalized x1, int8 (x*127)
__device__ float              g_pos[NROWS];
__device__ unsigned long long g_acc = 0;           // fixed-point loss accumulator
__device__ unsigned int       g_arr = 0;           // barrier arrivals
__device__ volatile unsigned int g_rel = 0;        // barrier release generation

// Canonical grid barrier (cooperative-groups pattern): __syncthreads chains
// every thread's prior writes to thread 0, whose __threadfence + atomic
// publishes them; waiters acquire via fence after the spin. Release counter
// is monotonic -> safe across graph replays; arrivals reset by last arriver.
__device__ __forceinline__ void grid_barrier(int G) {
    __syncthreads();
    if (threadIdx.x == 0) {
        unsigned int before = g_rel;
        __threadfence();
        unsigned int t = atomicAdd(&g_arr, 1u);
        if (t == (unsigned int)G - 1) {
            g_arr = 0;
            __threadfence();
            atomicAdd((unsigned int*)&g_rel, 1u);
        } else {
            while (g_rel == before) { __nanosleep(64); }
        }
        __threadfence();
    }
    __syncthreads();
}

__global__ void __launch_bounds__(256) fused_kernel(const float* __restrict__ x1,
                                                    const float* __restrict__ x2,
                                                    const int*   __restrict__ neg_idx,
                                                    float* __restrict__ out,
                                                    int G) {
    __shared__ float s1s[8][32];
    __shared__ float s2s[8][32];
    __shared__ float pss[8][32];
    __shared__ int   sidx[8][KNEG];
    __shared__ float lsum[8];

    int lane = threadIdx.x & 31;
    int warp = threadIdx.x >> 5;

    // ---------------- Phase A: normalize (r4 layout, int8 table) ----------
    for (int chunk = blockIdx.x; chunk < NCHUNK_A; chunk += G) {
        int n = chunk * 32 + lane;          // lane = row within chunk
        int part = warp;                    // warp = dim chunk [8w, 8w+8)
        int b  = n / HW;
        int hw = n - b * HW;
        const float* p1 = x1 + (size_t)b * DHW + (size_t)(part * 8) * HW + hw;
        const float* p2 = x2 + (size_t)b * DHW + (size_t)(part * 8) * HW + hw;

        float v1[8], v2[8];
        #pragma unroll
        for (int i = 0; i < 8; i++) v1[i] = p1[i * HW];
        #pragma unroll
        for (int i = 0; i < 8; i++) v2[i] = p2[i * HW];

        float s1 = 0.f, s2 = 0.f;
        #pragma unroll
        for (int i = 0; i < 8; i++) {
            s1 = fmaf(v1[i], v1[i], s1);
            s2 = fmaf(v2[i], v2[i], s2);
        }
        s1s[part][lane] = s1;
        s2s[part][lane] = s2;
        __syncthreads();

        float t1 = 0.f, t2 = 0.f;
        #pragma unroll
        for (int p = 0; p < 8; p++) { t1 += s1s[p][lane]; t2 += s2s[p][lane]; }
        float sc1 = 1.0f / fmaxf(sqrtf(t1), 1e-12f);
        float sc2 = 1.0f / fmaxf(sqrtf(t2), 1e-12f);

        float pos = 0.f;
        unsigned int w0 = 0, w1 = 0;
        #pragma unroll
        for (int i = 0; i < 8; i++) {
            float a = v1[i] * sc1;
            float c = v2[i] * sc2;
            pos += __expf(a * c);
            unsigned int q = (unsigned int)(__float2int_rn(a * 127.0f)) & 0xffu;
            if (i < 4) w0 |= q << (8 * i);
            else       w1 |= q << (8 * (i - 4));
        }
        *(uint2*)(g_x1q + (size_t)n * DIM + part * 8) = make_uint2(w0, w1);

        pss[part][lane] = pos;
        __syncthreads();
        if (part == 0) {
            float pt = 0.f;
            #pragma unroll
            for (int p = 0; p < 8; p++) pt += pss[p][lane];
            g_pos[n] = pt;
        }
        __syncthreads();   // protect smem reuse across chunk iterations
    }

    // table + pos visible to all blocks
    grid_barrier(G);

    // ---------------- Phase B: negatives (r14 dp4a body) ------------------
    float wsum = 0.f;      // per-warp (lane 0) running loss sum
    int grp = lane >> 2;   // which of 8 concurrent k's
    int sub = lane & 3;    // 16-dim chunk
    const float scale = 1.0f / 16129.0f;   // 1/127^2

    for (int chunk = blockIdx.x; chunk < NCHUNK_B; chunk += G) {
        int n = chunk * 8 + warp;

        for (int k = lane; k < KNEG; k += 32)
            sidx[warp][k] = neg_idx[(size_t)n * KNEG + k];
        __syncwarp();

        int4 qv = ((const int4*)(g_x1q + (size_t)n * DIM))[sub];

        float negacc = 0.f;
        #pragma unroll
        for (int it = 0; it < 13; it++) {
            int k = it * 8 + grp;
            bool valid = (k < KNEG);
            int j = sidx[warp][valid ? k : (KNEG - 1)];
            int4 bv = ((const int4*)(g_x1q + (size_t)j * DIM))[sub];
            int acc = 0;
            acc = __dp4a(qv.x, bv.x, acc);
            acc = __dp4a(qv.y, bv.y, acc);
            acc = __dp4a(qv.z, bv.z, acc);
            acc = __dp4a(qv.w, bv.w, acc);
            float p = (float)acc;
            p += __shfl_xor_sync(0xffffffffu, p, 2);
            p += __shfl_xor_sync(0xffffffffu, p, 1);
            float e = __expf(p * scale);
            negacc += valid ? e : 0.f;
        }
        negacc += __shfl_xor_sync(0xffffffffu, negacc, 4);
        negacc += __shfl_xor_sync(0xffffffffu, negacc, 8);
        negacc += __shfl_xor_sync(0xffffffffu, negacc, 16);

        if (lane == 0) {
            float pos = g_pos[n];
            wsum += logf(pos + negacc) - logf(pos);
        }
        __syncwarp();      // protect sidx[warp] reuse next iteration
    }

    // block-local combine -> one deterministic integer atomic per block
    if (lane == 0) lsum[warp] = wsum;
    __syncthreads();
    if (threadIdx.x == 0) {
        float s = 0.f;
        #pragma unroll
        for (int w = 0; w < 8; w++) s += lsum[w];
        atomicAdd(&g_acc, (unsigned long long)(s * FXSCALE));
    }

    // all atomics done
    grid_barrier(G);

    if (blockIdx.x == 0 && threadIdx.x == 0) {
        unsigned long long tot = atomicExch(&g_acc, 0ULL);  // read + reset for replay
        out[0] = (float)((double)tot / (double)FXSCALE / (double)NROWS);
    }
}

extern "C" void kernel_launch(void* const* d_in, const int* in_sizes, int n_in,
                              void* d_out, int out_size) {
    const float* x1      = (const float*)d_in[0];
    const float* x2      = (const float*)d_in[1];
    const int*   neg_idx = (const int*)  d_in[2];
    float*       out     = (float*)d_out;

    int dev = 0;
    cudaGetDevice(&dev);
    int sms = 148;
    cudaDeviceGetAttribute(&sms, cudaDevAttrMultiProcessorCount, dev);
    int bpm = 1;
    cudaOccupancyMaxActiveBlocksPerMultiprocessor(&bpm, fused_kernel, 256, 0);
    if (bpm < 1) bpm = 1;
    int G = sms * bpm;                 // guaranteed co-resident
    if (G > NCHUNK_B) G = NCHUNK_B;    // never more blocks than phase-B chunks

    fused_kernel<<<G, 256>>>(x1, x2, neg_idx, out, G);
}